// round 1
// baseline (speedup 1.0000x reference)
#include <cuda_runtime.h>

// Problem constants
constexpr int cN = 268;    // tokens
constexpr int cS = 32;     // snapshots per branch
constexpr int cE = 1024;   // embed
constexpr int cF = 1024;   // feature
constexpr int cB = 4;      // branches
constexpr int cT2 = 4;     // second-stage "time" = branches
constexpr float cScale = 0.03125f;  // 1/sqrt(1024)

// GEMM tiling
constexpr int BM = 64, BN = 64, BK = 16;
constexpr int TM = 4, TN = 4;   // 16x16 threads, 4x4 each

// ---------------- scratch (device globals; no allocation allowed) ----------
__device__ float g_q [5 * cN * cE];                 // per-branch q (4) + shared q (1)
__device__ float g_K [cB * cS * cN * cE];           // stage-1 keys
__device__ float g_V [cB * cS * cN * cE];           // stage-1 values
__device__ float g_Sc[cB * cS * cN * cN];           // stage-1 scores
__device__ float g_ms[cB * cN * cE];                // branch outputs
__device__ float g_K2[cT2 * cN * cE];
__device__ float g_V2[cT2 * cN * cE];
__device__ float g_S2[cT2 * cN * cN];

// ---------------- generic tiled GEMM body ----------------------------------
// C[M,Nc] = alpha * A[M,K] * B  (BT=false: B is K x Nc; BT=true: B is Nc x K, C=A*B^T)
template <bool BT>
__device__ __forceinline__ void gemm_tile(const float* __restrict__ A,
                                          const float* __restrict__ B,
                                          float* __restrict__ C,
                                          int M, int K, int Nc, float alpha)
{
    __shared__ float As[BK][BM + 4];
    __shared__ float Bs[BK][BN + 4];

    const int tid = threadIdx.x;
    const int tx = tid & 15, ty = tid >> 4;
    const int row0 = blockIdx.y * BM;
    const int col0 = blockIdx.x * BN;

    float acc[TM][TN] = {};

    for (int k0 = 0; k0 < K; k0 += BK) {
        // A tile: BM x BK
#pragma unroll
        for (int j = 0; j < (BM * BK) / 256; ++j) {
            int i = tid + j * 256;
            int r = i / BK, c = i % BK;
            int gr = row0 + r, gc = k0 + c;
            As[c][r] = (gr < M && gc < K) ? A[(size_t)gr * K + gc] : 0.f;
        }
        // B tile
        if (!BT) {
#pragma unroll
            for (int j = 0; j < (BN * BK) / 256; ++j) {
                int i = tid + j * 256;
                int r = i / BN, c = i % BN;   // r: k index, c: n index
                int gk = k0 + r, gc = col0 + c;
                Bs[r][c] = (gk < K && gc < Nc) ? B[(size_t)gk * Nc + gc] : 0.f;
            }
        } else {
#pragma unroll
            for (int j = 0; j < (BN * BK) / 256; ++j) {
                int i = tid + j * 256;
                int r = i / BK, c = i % BK;   // r: n index, c: k index
                int gn = col0 + r, gk = k0 + c;
                Bs[c][r] = (gn < Nc && gk < K) ? B[(size_t)gn * K + gk] : 0.f;
            }
        }
        __syncthreads();

#pragma unroll
        for (int kk = 0; kk < BK; ++kk) {
            float a[TM], b[TN];
#pragma unroll
            for (int i = 0; i < TM; ++i) a[i] = As[kk][ty * TM + i];
#pragma unroll
            for (int j = 0; j < TN; ++j) b[j] = Bs[kk][tx * TN + j];
#pragma unroll
            for (int i = 0; i < TM; ++i)
#pragma unroll
                for (int j = 0; j < TN; ++j) acc[i][j] += a[i] * b[j];
        }
        __syncthreads();
    }

#pragma unroll
    for (int i = 0; i < TM; ++i) {
        int gr = row0 + ty * TM + i;
        if (gr < M) {
#pragma unroll
            for (int j = 0; j < TN; ++j) {
                int gc = col0 + tx * TN + j;
                if (gc < Nc) C[(size_t)gr * Nc + gc] = alpha * acc[i][j];
            }
        }
    }
}

// ---------------- stage kernels --------------------------------------------

// z in [0,5): z<4 -> q_b = features @ wq_b[z]; z==4 -> shared q = features @ wq
__global__ __launch_bounds__(256) void q_gemm_kernel(const float* __restrict__ features,
                                                     const float* __restrict__ wq_b,
                                                     const float* __restrict__ wq)
{
    int z = blockIdx.z;
    const float* W = (z < 4) ? (wq_b + (size_t)z * cF * cE) : wq;
    gemm_tile<false>(features, W, g_q + (size_t)z * cN * cE, cN, cF, cE, 1.f);
}

// z in [0,8): branch = z&3, kv = z>>2.  K/V[branch] = s_branch @ w{k,v}_b[branch]
__global__ __launch_bounds__(256) void kv_gemm_kernel(const float* __restrict__ s1,
                                                      const float* __restrict__ s2,
                                                      const float* __restrict__ s3,
                                                      const float* __restrict__ s4,
                                                      const float* __restrict__ wk_b,
                                                      const float* __restrict__ wv_b)
{
    int z = blockIdx.z;
    int br = z & 3, kv = z >> 2;
    const float* sarr[4] = {s1, s2, s3, s4};
    const float* A = sarr[br];
    const float* W = (kv ? wv_b : wk_b) + (size_t)br * cE * cE;
    float* Cp = (kv ? g_V : g_K) + (size_t)br * cS * cN * cE;
    gemm_tile<false>(A, W, Cp, cS * cN, cE, cE, 1.f);
}

// z in [0,128): b = z>>5, t = z&31.  Sc[b,t] = scale * q_b @ K[b,t]^T
__global__ __launch_bounds__(256) void scores1_kernel()
{
    int z = blockIdx.z;
    int b = z >> 5;
    gemm_tile<true>(g_q + (size_t)b * cN * cE,
                    g_K + (size_t)z * cN * cE,
                    g_Sc + (size_t)z * cN * cN,
                    cN, cE, cN, cScale);
}

// warp-per-row softmax over rows of length cN (=268, 9 elems/lane)
template <int STAGE>
__global__ __launch_bounds__(256) void softmax_kernel(int rows)
{
    int w = (blockIdx.x * blockDim.x + threadIdx.x) >> 5;
    int lane = threadIdx.x & 31;
    if (w >= rows) return;
    float* row = (STAGE == 0 ? g_Sc : g_S2) + (size_t)w * cN;

    float v[9];
    float m = -1e30f;
#pragma unroll
    for (int j = 0; j < 9; ++j) {
        int c = lane + 32 * j;
        v[j] = (c < cN) ? row[c] : -1e30f;
        m = fmaxf(m, v[j]);
    }
#pragma unroll
    for (int o = 16; o; o >>= 1) m = fmaxf(m, __shfl_xor_sync(0xffffffffu, m, o));
    float s = 0.f;
#pragma unroll
    for (int j = 0; j < 9; ++j) { v[j] = expf(v[j] - m); s += v[j]; }
#pragma unroll
    for (int o = 16; o; o >>= 1) s += __shfl_xor_sync(0xffffffffu, s, o);
    float inv = 1.f / s;
#pragma unroll
    for (int j = 0; j < 9; ++j) {
        int c = lane + 32 * j;
        if (c < cN) row[c] = v[j] * inv;
    }
}

// C = sum_t A_t(kN x kN) @ B_t(kN x kE).
// STAGE 0: per-branch (z), A=g_Sc, B=g_V, C=g_ms, T=cS.
// STAGE 1: A=g_S2, B=g_V2, C=outp, T=cT2.
template <int STAGE>
__global__ __launch_bounds__(256) void av_kernel(float* __restrict__ outp)
{
    __shared__ float As[BK][BM + 4];
    __shared__ float Bs[BK][BN + 4];

    const int z = blockIdx.z;
    const float* A0; const float* B0; float* C; int T;
    if (STAGE == 0) {
        A0 = g_Sc + (size_t)z * cS * cN * cN;
        B0 = g_V  + (size_t)z * cS * cN * cE;
        C  = g_ms + (size_t)z * cN * cE;
        T = cS;
    } else {
        A0 = g_S2; B0 = g_V2; C = outp; T = cT2;
    }

    const int tid = threadIdx.x;
    const int tx = tid & 15, ty = tid >> 4;
    const int row0 = blockIdx.y * BM;
    const int col0 = blockIdx.x * BN;

    float acc[TM][TN] = {};

    for (int t = 0; t < T; ++t) {
        const float* A = A0 + (size_t)t * cN * cN;
        const float* B = B0 + (size_t)t * cN * cE;
        for (int k0 = 0; k0 < cN; k0 += BK) {
#pragma unroll
            for (int j = 0; j < (BM * BK) / 256; ++j) {
                int i = tid + j * 256;
                int r = i / BK, c = i % BK;
                int gr = row0 + r, gc = k0 + c;
                As[c][r] = (gr < cN && gc < cN) ? A[(size_t)gr * cN + gc] : 0.f;
            }
#pragma unroll
            for (int j = 0; j < (BN * BK) / 256; ++j) {
                int i = tid + j * 256;
                int r = i / BN, c = i % BN;     // r: k index (token m), c: e index
                int gk = k0 + r, gc = col0 + c;
                Bs[r][c] = (gk < cN) ? B[(size_t)gk * cE + gc] : 0.f;
            }
            __syncthreads();
#pragma unroll
            for (int kk = 0; kk < BK; ++kk) {
                float a[TM], b[TN];
#pragma unroll
                for (int i = 0; i < TM; ++i) a[i] = As[kk][ty * TM + i];
#pragma unroll
                for (int j = 0; j < TN; ++j) b[j] = Bs[kk][tx * TN + j];
#pragma unroll
                for (int i = 0; i < TM; ++i)
#pragma unroll
                    for (int j = 0; j < TN; ++j) acc[i][j] += a[i] * b[j];
            }
            __syncthreads();
        }
    }

#pragma unroll
    for (int i = 0; i < TM; ++i) {
        int gr = row0 + ty * TM + i;
        if (gr < cN) {
#pragma unroll
            for (int j = 0; j < TN; ++j)
                C[(size_t)gr * cE + col0 + tx * TN + j] = acc[i][j];
        }
    }
}

// z in [0,2): K2/V2 = g_ms(1072 x 1024) @ {wk,wv}
__global__ __launch_bounds__(256) void stage2_kv_kernel(const float* __restrict__ wk,
                                                        const float* __restrict__ wv)
{
    int z = blockIdx.z;
    gemm_tile<false>(g_ms, z ? wv : wk, z ? g_V2 : g_K2, cT2 * cN, cE, cE, 1.f);
}

// z in [0,4): S2[t] = scale * q_shared @ K2[t]^T
__global__ __launch_bounds__(256) void scores2_kernel()
{
    int z = blockIdx.z;
    gemm_tile<true>(g_q + (size_t)4 * cN * cE,
                    g_K2 + (size_t)z * cN * cE,
                    g_S2 + (size_t)z * cN * cN,
                    cN, cE, cN, cScale);
}

// ---------------- launch ----------------------------------------------------
extern "C" void kernel_launch(void* const* d_in, const int* in_sizes, int n_in,
                              void* d_out, int out_size)
{
    const float* features = (const float*)d_in[0];
    const float* s1   = (const float*)d_in[1];
    const float* s2   = (const float*)d_in[2];
    const float* s3   = (const float*)d_in[3];
    const float* s4   = (const float*)d_in[4];
    const float* wq_b = (const float*)d_in[5];
    const float* wk_b = (const float*)d_in[6];
    const float* wv_b = (const float*)d_in[7];
    const float* wq   = (const float*)d_in[8];
    const float* wk   = (const float*)d_in[9];
    const float* wv   = (const float*)d_in[10];
    float* out = (float*)d_out;

    const dim3 thr(256);
    const int MT_N = (cN + BM - 1) / BM;          // 5 tiles over 268 rows
    const int NT_E = cE / BN;                     // 16 tiles over 1024 cols
    const int NT_N = (cN + BN - 1) / BN;          // 5 tiles over 268 cols

    // Stage 1
    q_gemm_kernel<<<dim3(NT_E, MT_N, 5), thr>>>(features, wq_b, wq);
    kv_gemm_kernel<<<dim3(NT_E, (cS * cN) / BM, 8), thr>>>(s1, s2, s3, s4, wk_b, wv_b);
    scores1_kernel<<<dim3(NT_N, MT_N, cB * cS), thr>>>();
    {
        int rows = cB * cS * cN;                  // 34304
        softmax_kernel<0><<<(rows + 7) / 8, 256>>>(rows);
    }
    av_kernel<0><<<dim3(NT_E, MT_N, cB), thr>>>(out);

    // Stage 2
    stage2_kv_kernel<<<dim3(NT_E, (cT2 * cN + BM - 1) / BM, 2), thr>>>(wk, wv);
    scores2_kernel<<<dim3(NT_N, MT_N, cT2), thr>>>();
    {
        int rows = cT2 * cN;                      // 1072
        softmax_kernel<1><<<(rows + 7) / 8, 256>>>(rows);
    }
    av_kernel<1><<<dim3(NT_E, MT_N, 1), thr>>>(out);
}

// round 4
// speedup vs baseline: 3.0007x; 3.0007x over previous
#include <cuda_runtime.h>
#include <stdint.h>

// ---------------- problem constants ----------------------------------------
constexpr int cN = 268, cS = 32, cE = 1024, cB = 4;
constexpr float cScale = 0.03125f;           // 1/sqrt(1024)
constexpr size_t MM  = 1024ull * 1024ull;    // one 1024x1024 matrix
constexpr int   TNK  = cS * cN;              // 8576
constexpr size_t NE  = (size_t)cN * cE;      // 274432

// ---------------- scratch (device globals) ----------------------------------
__device__ __align__(1024) float g_WT[15 * MM];                    // transposed weights [N,K]
__device__ __align__(1024) float g_q [5 * cN * cE];                // q per branch + shared
__device__ __align__(1024) float g_K [(size_t)cB * TNK * cE];      // stage1 K  [b][tm][e]
__device__ __align__(1024) float g_V [(size_t)cB * TNK * cE];      // stage1 V  [b][tm][e]
__device__ __align__(1024) float g_Vt[(size_t)cB * cE * TNK];      // Vt        [b][e][tm]
__device__ __align__(1024) float g_P [(size_t)cB * cN * TNK];      // probs     [b][n][t][m]
__device__ __align__(1024) float g_ms[(size_t)cB * cN * cE];       // branch outputs
__device__ __align__(1024) float g_K2[(size_t)4 * cN * cE];
__device__ __align__(1024) float g_V2[(size_t)4 * cN * cE];
__device__ __align__(1024) float g_V2t[(size_t)cE * 4 * cN];
__device__ __align__(1024) float g_P2[(size_t)cN * 4 * cN];        // [n][t][m]

// ---------------- PTX helpers -----------------------------------------------
__device__ __forceinline__ uint32_t smem_u32(const void* p) {
    uint32_t a;
    asm("{ .reg .u64 t; cvta.to.shared.u64 t, %1; cvt.u32.u64 %0, t; }" : "=r"(a) : "l"(p));
    return a;
}
__device__ __forceinline__ void cp16(uint32_t dst, const void* src, int nbytes) {
    asm volatile("cp.async.cg.shared.global [%0], [%1], 16, %2;"
                 :: "r"(dst), "l"(src), "r"(nbytes));
}
__device__ __forceinline__ uint32_t f2tf32(float f) {
    uint32_t r;
    asm("cvt.rna.tf32.f32 %0, %1;" : "=r"(r) : "f"(f));
    return r;
}
__device__ __forceinline__ void mma_tf32(float* c, const uint32_t* a, const uint32_t* b) {
    asm volatile(
        "mma.sync.aligned.m16n8k8.row.col.f32.tf32.tf32.f32 "
        "{%0,%1,%2,%3}, {%4,%5,%6,%7}, {%8,%9}, {%0,%1,%2,%3};"
        : "+f"(c[0]), "+f"(c[1]), "+f"(c[2]), "+f"(c[3])
        : "r"(a[0]), "r"(a[1]), "r"(a[2]), "r"(a[3]), "r"(b[0]), "r"(b[1]));
}

// ---------------- tf32 mma.sync NT GEMM -------------------------------------
// C[M,Nv] = alpha * A[M,K] * B[Nv,K]^T     (A,B row-major packed: row stride = K)
// batch z: off = (z>>zShift)*Hi + (z & ((1<<zShift)-1))*Lo  per operand.
struct GArgs {
    const float* A; const float* B; float* C;
    int M, Nv, K; long ldc;
    int zShift;
    long aHi, aLo, bHi, bLo, cHi, cLo;
    float alpha;
};

constexpr int TM_ = 128, TN_ = 128, TK_ = 32;
constexpr int STAGE_F    = TM_ * TK_ + TN_ * TK_;         // floats per stage (A + B)
constexpr int SMEM_BYTES = 2 * STAGE_F * 4;               // 65536

// swizzled index for element (r, c) in a [rows][32] float tile
__device__ __forceinline__ int sw_idx(int r, int c) {
    return r * 32 + ((((c >> 2) ^ (r & 7)) << 2) | (c & 3));
}

__global__ void __launch_bounds__(256) gemm_tc(GArgs g)
{
    extern __shared__ __align__(128) float smem[];
    const uint32_t sbase = smem_u32(smem);
    const int tid  = threadIdx.x;
    const int wid  = tid >> 5, lane = tid & 31;
    const int grp  = lane >> 2, tg = lane & 3;

    const int z  = blockIdx.z;
    const long zh = z >> g.zShift;
    const long zl = z & ((1 << g.zShift) - 1);
    const float* A = g.A + zh * g.aHi + zl * g.aLo;
    const float* B = g.B + zh * g.bHi + zl * g.bLo;
    float* C = g.C + zh * g.cHi + zl * g.cLo;

    const int m0 = blockIdx.y * TM_, n0 = blockIdx.x * TN_;
    const int M = g.M, Nv = g.Nv, K = g.K;
    const int nchunks = (K + TK_ - 1) / TK_;

    // warp tile: 64 rows x 32 cols; warps arranged 2 (m) x 4 (n)
    const int wrow0 = (wid & 1) * 64;
    const int wcol0 = (wid >> 1) * 32;

    float acc[4][4][4] = {};   // [mt][nt][frag]

    auto load_chunk = [&](int buf, int c) {
        const long k0 = (long)c * TK_;
        const uint32_t sA = sbase + buf * (STAGE_F * 4);
        const uint32_t sB = sA + TM_ * TK_ * 4;
        // A: 128 rows x 8 segs(16B); 1024 segs / 256 thr = 4 each
#pragma unroll
        for (int i = 0; i < 4; ++i) {
            int l = tid + i * 256, r = l >> 3, seg = l & 7;
            long grow = m0 + r, gk = k0 + seg * 4;
            bool ok = (grow < M) && (gk < K);
            const float* src = ok ? (A + grow * (long)K + gk) : A;
            uint32_t off = (uint32_t)(r * 128 + (seg ^ (r & 7)) * 16);
            cp16(sA + off, src, ok ? 16 : 0);
        }
        // B: 128 rows
#pragma unroll
        for (int i = 0; i < 4; ++i) {
            int l = tid + i * 256, r = l >> 3, seg = l & 7;
            long grow = n0 + r, gk = k0 + seg * 4;
            bool ok = (grow < Nv) && (gk < K);
            const float* src = ok ? (B + grow * (long)K + gk) : B;
            uint32_t off = (uint32_t)(r * 128 + (seg ^ (r & 7)) * 16);
            cp16(sB + off, src, ok ? 16 : 0);
        }
        asm volatile("cp.async.commit_group;");
    };

    load_chunk(0, 0);
    for (int c = 0; c < nchunks; ++c) {
        if (c + 1 < nchunks) {
            load_chunk((c + 1) & 1, c + 1);
            asm volatile("cp.async.wait_group 1;");
        } else {
            asm volatile("cp.async.wait_group 0;");
        }
        __syncthreads();

        const float* As = smem + (c & 1) * STAGE_F;
        const float* Bs = As + TM_ * TK_;
#pragma unroll
        for (int ks = 0; ks < 4; ++ks) {
            const int k0 = ks * 8;
            uint32_t af[4][4], bf[4][2];
#pragma unroll
            for (int mt = 0; mt < 4; ++mt) {
                int r0 = wrow0 + mt * 16 + grp;
                af[mt][0] = f2tf32(As[sw_idx(r0,     k0 + tg)]);
                af[mt][1] = f2tf32(As[sw_idx(r0 + 8, k0 + tg)]);
                af[mt][2] = f2tf32(As[sw_idx(r0,     k0 + tg + 4)]);
                af[mt][3] = f2tf32(As[sw_idx(r0 + 8, k0 + tg + 4)]);
            }
#pragma unroll
            for (int nt = 0; nt < 4; ++nt) {
                int rn = wcol0 + nt * 8 + grp;
                bf[nt][0] = f2tf32(Bs[sw_idx(rn, k0 + tg)]);
                bf[nt][1] = f2tf32(Bs[sw_idx(rn, k0 + tg + 4)]);
            }
#pragma unroll
            for (int mt = 0; mt < 4; ++mt)
#pragma unroll
                for (int nt = 0; nt < 4; ++nt)
                    mma_tf32(acc[mt][nt], af[mt], bf[nt]);
        }
        __syncthreads();
    }

    // epilogue
    const float alpha = g.alpha;
#pragma unroll
    for (int mt = 0; mt < 4; ++mt) {
#pragma unroll
        for (int nt = 0; nt < 4; ++nt) {
            long r0 = m0 + wrow0 + mt * 16 + grp;
            long cc = n0 + wcol0 + nt * 8 + tg * 2;
            if (cc < Nv) {
                if (r0 < M) {
                    C[r0 * g.ldc + cc]     = alpha * acc[mt][nt][0];
                    C[r0 * g.ldc + cc + 1] = alpha * acc[mt][nt][1];
                }
                if (r0 + 8 < M) {
                    C[(r0 + 8) * g.ldc + cc]     = alpha * acc[mt][nt][2];
                    C[(r0 + 8) * g.ldc + cc + 1] = alpha * acc[mt][nt][3];
                }
            }
        }
    }
}

// ---------------- transposes -------------------------------------------------
__global__ void transpose_w(const float* __restrict__ wq_b, const float* __restrict__ wk_b,
                            const float* __restrict__ wv_b, const float* __restrict__ wq,
                            const float* __restrict__ wk,   const float* __restrict__ wv)
{
    __shared__ float t[32][33];
    const int z = blockIdx.z;
    const float* src = (z < 4)  ? wq_b + (size_t)z * MM
                     : (z < 8)  ? wk_b + (size_t)(z - 4) * MM
                     : (z < 12) ? wv_b + (size_t)(z - 8) * MM
                     : (z == 12) ? wq : (z == 13) ? wk : wv;
    float* dst = g_WT + (size_t)z * MM;
    const int x0 = blockIdx.x * 32, y0 = blockIdx.y * 32;
#pragma unroll
    for (int i = threadIdx.y; i < 32; i += 8)
        t[i][threadIdx.x] = src[(size_t)(y0 + i) * 1024 + x0 + threadIdx.x];
    __syncthreads();
#pragma unroll
    for (int i = threadIdx.y; i < 32; i += 8)
        dst[(size_t)(x0 + i) * 1024 + y0 + threadIdx.x] = t[threadIdx.x][i];
}

// dst[c*R + r] = src[r*Cc + c], guarded; batched via strides
__global__ void transpose_g(const float* __restrict__ src, float* __restrict__ dst,
                            int R, int Cc, size_t sB, size_t dB)
{
    __shared__ float t[32][33];
    src += (size_t)blockIdx.z * sB;
    dst += (size_t)blockIdx.z * dB;
    const int x0 = blockIdx.x * 32, y0 = blockIdx.y * 32;
#pragma unroll
    for (int i = threadIdx.y; i < 32; i += 8) {
        int y = y0 + i, x = x0 + threadIdx.x;
        t[i][threadIdx.x] = (y < R && x < Cc) ? src[(size_t)y * Cc + x] : 0.f;
    }
    __syncthreads();
#pragma unroll
    for (int i = threadIdx.y; i < 32; i += 8) {
        int x = x0 + i, y = y0 + threadIdx.x;
        if (x < Cc && y < R) dst[(size_t)x * R + y] = t[threadIdx.x][i];
    }
}

// ---------------- softmax (warp per row of 268) ------------------------------
__global__ __launch_bounds__(256) void softmax_kernel(float* __restrict__ base, int rows)
{
    int w = (blockIdx.x * blockDim.x + threadIdx.x) >> 5;
    int lane = threadIdx.x & 31;
    if (w >= rows) return;
    float* row = base + (size_t)w * cN;

    float v[9];
    float m = -1e30f;
#pragma unroll
    for (int j = 0; j < 9; ++j) {
        int c = lane + 32 * j;
        v[j] = (c < cN) ? row[c] : -1e30f;
        m = fmaxf(m, v[j]);
    }
#pragma unroll
    for (int o = 16; o; o >>= 1) m = fmaxf(m, __shfl_xor_sync(0xffffffffu, m, o));
    float s = 0.f;
#pragma unroll
    for (int j = 0; j < 9; ++j) { v[j] = expf(v[j] - m); s += v[j]; }
#pragma unroll
    for (int o = 16; o; o >>= 1) s += __shfl_xor_sync(0xffffffffu, s, o);
    float inv = 1.f / s;
#pragma unroll
    for (int j = 0; j < 9; ++j) {
        int c = lane + 32 * j;
        if (c < cN) row[c] = v[j] * inv;
    }
}

// ---------------- launch -----------------------------------------------------
static inline void launch_gemm(const GArgs& a, int batch)
{
    dim3 grid((a.Nv + TN_ - 1) / TN_, (a.M + TM_ - 1) / TM_, batch);
    gemm_tc<<<grid, 256, SMEM_BYTES>>>(a);
}

extern "C" void kernel_launch(void* const* d_in, const int* in_sizes, int n_in,
                              void* d_out, int out_size)
{
    const float* features = (const float*)d_in[0];
    const float* s_in[4]  = { (const float*)d_in[1], (const float*)d_in[2],
                              (const float*)d_in[3], (const float*)d_in[4] };
    const float* wq_b = (const float*)d_in[5];
    const float* wk_b = (const float*)d_in[6];
    const float* wv_b = (const float*)d_in[7];
    const float* wq   = (const float*)d_in[8];
    const float* wk   = (const float*)d_in[9];
    const float* wv   = (const float*)d_in[10];
    float* out = (float*)d_out;

    cudaFuncSetAttribute(gemm_tc, cudaFuncAttributeMaxDynamicSharedMemorySize, SMEM_BYTES);

    float *WT, *Q, *Kb, *Vb, *Vt, *P, *MS, *K2, *V2, *V2t, *P2;
    cudaGetSymbolAddress((void**)&WT,  g_WT);
    cudaGetSymbolAddress((void**)&Q,   g_q);
    cudaGetSymbolAddress((void**)&Kb,  g_K);
    cudaGetSymbolAddress((void**)&Vb,  g_V);
    cudaGetSymbolAddress((void**)&Vt,  g_Vt);
    cudaGetSymbolAddress((void**)&P,   g_P);
    cudaGetSymbolAddress((void**)&MS,  g_ms);
    cudaGetSymbolAddress((void**)&K2,  g_K2);
    cudaGetSymbolAddress((void**)&V2,  g_V2);
    cudaGetSymbolAddress((void**)&V2t, g_V2t);
    cudaGetSymbolAddress((void**)&P2,  g_P2);

    // 0) transpose all weights -> [N,K]
    transpose_w<<<dim3(32, 32, 15), dim3(32, 8)>>>(wq_b, wk_b, wv_b, wq, wk, wv);

    // 1) q projections: branches 0..3 batched + shared
    launch_gemm({features, WT, Q, cN, 1024, 1024, 1024,
                 0, 0, 0, (long)MM, 0, (long)NE, 0, 1.f}, 4);
    launch_gemm({features, WT + 12 * MM, Q + 4 * NE, cN, 1024, 1024, 1024,
                 0, 0, 0, 0, 0, 0, 0, 1.f}, 1);

    // 2) stage-1 K/V projections (8 launches)
    for (int kv = 0; kv < 2; ++kv)
        for (int br = 0; br < 4; ++br) {
            const float* Wp = WT + (size_t)(4 + 4 * kv + br) * MM;
            float* Cp = (kv ? Vb : Kb) + (size_t)br * TNK * cE;
            launch_gemm({s_in[br], Wp, Cp, TNK, 1024, 1024, 1024,
                         0, 0, 0, 0, 0, 0, 0, 1.f}, 1);
        }

    // 3) stage-1 scores -> P[b][n][t][m], scaled
    launch_gemm({Q, Kb, P, cN, cN, 1024, (long)TNK,
                 5, (long)NE, 0,
                 (long)TNK * cE, (long)cN * cE,
                 (long)cN * TNK, (long)cN, cScale}, cB * cS);

    // 4) softmax over 34304 rows of 268
    {
        int rows = cB * cN * cS;
        softmax_kernel<<<(rows + 7) / 8, 256>>>(P, rows);
    }

    // 5) transpose V -> Vt[b][e][tm]
    transpose_g<<<dim3(32, TNK / 32, 4), dim3(32, 8)>>>(
        Vb, Vt, TNK, 1024, (size_t)TNK * cE, (size_t)cE * TNK);

    // 6) branch outputs: ms[b] = P[b] (268 x 8576) * Vt[b]^T  (K=8576)
    launch_gemm({P, Vt, MS, cN, 1024, TNK, 1024,
                 0, (long)cN * TNK, 0, (long)cE * TNK, 0, (long)NE, 0, 1.f}, 4);

    // 7) stage-2 K/V projections: (1072 x 1024) @ wk/wv^T
    launch_gemm({MS, WT + 13 * MM, K2, 4 * cN, 1024, 1024, 1024,
                 0, 0, 0, 0, 0, 0, 0, 1.f}, 1);
    launch_gemm({MS, WT + 14 * MM, V2, 4 * cN, 1024, 1024, 1024,
                 0, 0, 0, 0, 0, 0, 0, 1.f}, 1);

    // 8) stage-2 scores -> P2[n][t][m]
    launch_gemm({Q + 4 * NE, K2, P2, cN, cN, 1024, (long)4 * cN,
                 0, 0, 0, (long)cN * cE, 0, (long)cN, 0, cScale}, 4);

    // 9) softmax over 1072 rows
    softmax_kernel<<<(4 * cN + 7) / 8, 256>>>(P2, 4 * cN);

    // 10) transpose V2 -> V2t[e][tm]
    transpose_g<<<dim3(32, (4 * cN + 31) / 32, 1), dim3(32, 8)>>>(
        V2, V2t, 4 * cN, 1024, 0, 0);

    // 11) final: out = P2 (268 x 1072) * V2t^T  (K=1072)
    launch_gemm({P2, V2t, out, cN, 1024, 4 * cN, 1024,
                 0, 0, 0, 0, 0, 0, 0, 1.f}, 1);
}

// round 6
// speedup vs baseline: 3.3359x; 1.1117x over previous
#include <cuda_runtime.h>
#include <stdint.h>

// ---------------- problem constants ----------------------------------------
constexpr int cN = 268, cS = 32, cE = 1024, cB = 4;
constexpr float cScale = 0.03125f;           // 1/sqrt(1024)
constexpr size_t MM  = 1024ull * 1024ull;    // one 1024x1024 matrix
constexpr int   TNK  = cS * cN;              // 8576
constexpr size_t NE  = (size_t)cN * cE;      // 274432
constexpr size_t SNE = (size_t)TNK * cE;     // 8781824

// ---------------- scratch (device globals) ----------------------------------
__device__ __align__(1024) float g_WT[15 * MM];                    // transposed+rounded weights [N,K]
__device__ __align__(1024) float g_F [cN * cE];                    // rounded features
__device__ __align__(1024) float g_S [4 * SNE];                    // rounded snapshots, contiguous
__device__ __align__(1024) float g_q [5 * cN * cE];                // q per branch + shared
__device__ __align__(1024) float g_KV[2 * cB * SNE];               // [kv][b][tm][e]
__device__ __align__(1024) float g_Vt[(size_t)cB * cE * TNK];      // Vt [b][e][tm]
__device__ __align__(1024) float g_P [(size_t)cB * cN * TNK];      // probs [b][n][t][m]
__device__ __align__(1024) float g_ms[(size_t)cB * cN * cE];       // branch outputs
__device__ __align__(1024) float g_K2[(size_t)4 * cN * cE];
__device__ __align__(1024) float g_V2[(size_t)4 * cN * cE];
__device__ __align__(1024) float g_V2t[(size_t)cE * 4 * cN];
__device__ __align__(1024) float g_P2[(size_t)cN * 4 * cN];        // [n][t][m]

// ---------------- PTX helpers -----------------------------------------------
__device__ __forceinline__ uint32_t smem_u32(const void* p) {
    uint32_t a;
    asm("{ .reg .u64 t; cvta.to.shared.u64 t, %1; cvt.u32.u64 %0, t; }" : "=r"(a) : "l"(p));
    return a;
}
__device__ __forceinline__ void cp16(uint32_t dst, const void* src, int nbytes) {
    asm volatile("cp.async.cg.shared.global [%0], [%1], 16, %2;"
                 :: "r"(dst), "l"(src), "r"(nbytes));
}
__device__ __forceinline__ float roundtf(float f) {
    uint32_t r;
    asm("cvt.rna.tf32.f32 %0, %1;" : "=r"(r) : "f"(f));
    return __uint_as_float(r);
}
__device__ __forceinline__ void mma_tf32(float* c, const uint32_t* a, const uint32_t* b) {
    asm volatile(
        "mma.sync.aligned.m16n8k8.row.col.f32.tf32.tf32.f32 "
        "{%0,%1,%2,%3}, {%4,%5,%6,%7}, {%8,%9}, {%0,%1,%2,%3};"
        : "+f"(c[0]), "+f"(c[1]), "+f"(c[2]), "+f"(c[3])
        : "r"(a[0]), "r"(a[1]), "r"(a[2]), "r"(a[3]), "r"(b[0]), "r"(b[1]));
}

// ---------------- tf32 mma.sync NT GEMM -------------------------------------
// C[M,Nv] = alpha * A[M,K] * B[Nv,K]^T   (operands pre-rounded to tf32 in gmem)
// batch z: off = (z>>zShift)*Hi + (z & ((1<<zShift)-1))*Lo  per operand.
struct GArgs {
    const float* A; const float* B; float* C;
    int M, Nv, K; long ldc;
    int zShift;
    long aHi, aLo, bHi, bLo, cHi, cLo;
    int roundC;
    float alpha;
};

constexpr int TM_ = 128, TN_ = 128, TK_ = 32;
constexpr int STAGE_F    = TM_ * TK_ + TN_ * TK_;         // floats per stage (A + B)
constexpr int SMEM_BYTES = 2 * STAGE_F * 4;               // 65536

// swizzled index for element (r, c) in a [rows][32] float tile
__device__ __forceinline__ int sw_idx(int r, int c) {
    return r * 32 + ((((c >> 2) ^ (r & 7)) << 2) | (c & 3));
}

__global__ void __launch_bounds__(256, 2) gemm_tc(GArgs g)
{
    extern __shared__ __align__(128) float smem[];
    const uint32_t sbase = smem_u32(smem);
    const int tid  = threadIdx.x;
    const int wid  = tid >> 5, lane = tid & 31;
    const int grp  = lane >> 2, tg = lane & 3;

    const int z  = blockIdx.z;
    const long zh = z >> g.zShift;
    const long zl = z & ((1 << g.zShift) - 1);
    const float* A = g.A + zh * g.aHi + zl * g.aLo;
    const float* B = g.B + zh * g.bHi + zl * g.bLo;
    float* C = g.C + zh * g.cHi + zl * g.cLo;

    const int m0 = blockIdx.y * TM_, n0 = blockIdx.x * TN_;
    const int M = g.M, Nv = g.Nv, K = g.K;
    const int nchunks = (K + TK_ - 1) / TK_;

    // warp tile: 64 rows x 32 cols; warps arranged 2 (m) x 4 (n)
    const int wrow0 = (wid & 1) * 64;
    const int wcol0 = (wid >> 1) * 32;

    float acc[4][4][4] = {};   // [mt][nt][frag]

    auto load_chunk = [&](int buf, int c) {
        const long k0 = (long)c * TK_;
        const uint32_t sA = sbase + buf * (STAGE_F * 4);
        const uint32_t sB = sA + TM_ * TK_ * 4;
#pragma unroll
        for (int i = 0; i < 4; ++i) {
            int l = tid + i * 256, r = l >> 3, seg = l & 7;
            long grow = m0 + r, gk = k0 + seg * 4;
            bool ok = (grow < M) && (gk < K);
            const float* src = ok ? (A + grow * (long)K + gk) : A;
            uint32_t off = (uint32_t)(r * 128 + (seg ^ (r & 7)) * 16);
            cp16(sA + off, src, ok ? 16 : 0);
        }
#pragma unroll
        for (int i = 0; i < 4; ++i) {
            int l = tid + i * 256, r = l >> 3, seg = l & 7;
            long grow = n0 + r, gk = k0 + seg * 4;
            bool ok = (grow < Nv) && (gk < K);
            const float* src = ok ? (B + grow * (long)K + gk) : B;
            uint32_t off = (uint32_t)(r * 128 + (seg ^ (r & 7)) * 16);
            cp16(sB + off, src, ok ? 16 : 0);
        }
        asm volatile("cp.async.commit_group;");
    };

    load_chunk(0, 0);
    for (int c = 0; c < nchunks; ++c) {
        if (c + 1 < nchunks) {
            load_chunk((c + 1) & 1, c + 1);
            asm volatile("cp.async.wait_group 1;");
        } else {
            asm volatile("cp.async.wait_group 0;");
        }
        __syncthreads();

        const float* As = smem + (c & 1) * STAGE_F;
        const float* Bs = As + TM_ * TK_;
        // k-permutation: HW col t <- logical col 2t, HW col t+4 <- logical 2t+1.
        // Applied to both A and B identically; dot-product invariant.
        // Fragment pairs (tg, tg+4) thus sit in one contiguous 8-byte word.
#pragma unroll
        for (int ks = 0; ks < 4; ++ks) {
            const int cA = ks * 8 + 2 * tg;      // logical col pair base
            uint32_t af[4][4], bf[4][2];
#pragma unroll
            for (int mt = 0; mt < 4; ++mt) {
                int r0 = wrow0 + mt * 16 + grp;
                uint2 lo = *(const uint2*)&As[sw_idx(r0,     cA)];
                uint2 hi = *(const uint2*)&As[sw_idx(r0 + 8, cA)];
                af[mt][0] = lo.x; af[mt][1] = hi.x; af[mt][2] = lo.y; af[mt][3] = hi.y;
            }
#pragma unroll
            for (int nt = 0; nt < 4; ++nt) {
                int rn = wcol0 + nt * 8 + grp;
                uint2 bb = *(const uint2*)&Bs[sw_idx(rn, cA)];
                bf[nt][0] = bb.x; bf[nt][1] = bb.y;
            }
#pragma unroll
            for (int mt = 0; mt < 4; ++mt)
#pragma unroll
                for (int nt = 0; nt < 4; ++nt)
                    mma_tf32(acc[mt][nt], af[mt], bf[nt]);
        }
        __syncthreads();
    }

    // epilogue
    const float alpha = g.alpha;
    const int rC = g.roundC;
#pragma unroll
    for (int mt = 0; mt < 4; ++mt) {
#pragma unroll
        for (int nt = 0; nt < 4; ++nt) {
            long r0 = m0 + wrow0 + mt * 16 + grp;
            long cc = n0 + wcol0 + nt * 8 + tg * 2;
            if (cc < Nv) {
#pragma unroll
                for (int h = 0; h < 2; ++h) {
                    long rr = r0 + 8 * h;
                    if (rr < M) {
                        float v0 = alpha * acc[mt][nt][2 * h];
                        float v1 = alpha * acc[mt][nt][2 * h + 1];
                        if (rC) { v0 = roundtf(v0); v1 = roundtf(v1); }
                        C[rr * g.ldc + cc]     = v0;
                        C[rr * g.ldc + cc + 1] = v1;
                    }
                }
            }
        }
    }
}

// ---------------- input conversion (round to tf32) ---------------------------
__global__ void convert_inputs(const float* __restrict__ f,
                               const float* __restrict__ s1, const float* __restrict__ s2,
                               const float* __restrict__ s3, const float* __restrict__ s4)
{
    const int z = blockIdx.z;
    const float4* src; float4* dst; long n4;
    if (z == 0) {
        src = (const float4*)f;
        dst = (float4*)g_F;
        n4 = (long)(cN * cE) / 4;
    } else {
        const float* sp = (z == 1) ? s1 : (z == 2) ? s2 : (z == 3) ? s3 : s4;
        src = (const float4*)sp;
        dst = (float4*)(g_S + (size_t)(z - 1) * SNE);
        n4 = (long)SNE / 4;
    }
    for (long i = blockIdx.x * (long)blockDim.x + threadIdx.x; i < n4;
         i += (long)gridDim.x * blockDim.x) {
        float4 v = src[i];
        v.x = roundtf(v.x); v.y = roundtf(v.y);
        v.z = roundtf(v.z); v.w = roundtf(v.w);
        dst[i] = v;
    }
}

// ---------------- transposes (round on write) --------------------------------
__global__ void transpose_w(const float* __restrict__ wq_b, const float* __restrict__ wk_b,
                            const float* __restrict__ wv_b, const float* __restrict__ wq,
                            const float* __restrict__ wk,   const float* __restrict__ wv)
{
    __shared__ float t[32][33];
    const int z = blockIdx.z;
    const float* src = (z < 4)  ? wq_b + (size_t)z * MM
                     : (z < 8)  ? wk_b + (size_t)(z - 4) * MM
                     : (z < 12) ? wv_b + (size_t)(z - 8) * MM
                     : (z == 12) ? wq : (z == 13) ? wk : wv;
    float* dst = g_WT + (size_t)z * MM;
    const int x0 = blockIdx.x * 32, y0 = blockIdx.y * 32;
#pragma unroll
    for (int i = threadIdx.y; i < 32; i += 8)
        t[i][threadIdx.x] = src[(size_t)(y0 + i) * 1024 + x0 + threadIdx.x];
    __syncthreads();
#pragma unroll
    for (int i = threadIdx.y; i < 32; i += 8)
        dst[(size_t)(x0 + i) * 1024 + y0 + threadIdx.x] = roundtf(t[threadIdx.x][i]);
}

// dst[c*R + r] = round(src[r*Cc + c]), guarded; batched via strides
__global__ void transpose_g(const float* __restrict__ src, float* __restrict__ dst,
                            int R, int Cc, size_t sB, size_t dB)
{
    __shared__ float t[32][33];
    src += (size_t)blockIdx.z * sB;
    dst += (size_t)blockIdx.z * dB;
    const int x0 = blockIdx.x * 32, y0 = blockIdx.y * 32;
#pragma unroll
    for (int i = threadIdx.y; i < 32; i += 8) {
        int y = y0 + i, x = x0 + threadIdx.x;
        t[i][threadIdx.x] = (y < R && x < Cc) ? src[(size_t)y * Cc + x] : 0.f;
    }
    __syncthreads();
#pragma unroll
    for (int i = threadIdx.y; i < 32; i += 8) {
        int x = x0 + i, y = y0 + threadIdx.x;
        if (x < Cc && y < R) dst[(size_t)x * R + y] = roundtf(t[threadIdx.x][i]);
    }
}

// ---------------- softmax (warp per row of 268; rounds output) ---------------
__global__ __launch_bounds__(256) void softmax_kernel(float* __restrict__ base, int rows)
{
    int w = (blockIdx.x * blockDim.x + threadIdx.x) >> 5;
    int lane = threadIdx.x & 31;
    if (w >= rows) return;
    float* row = base + (size_t)w * cN;

    float v[9];
    float m = -1e30f;
#pragma unroll
    for (int j = 0; j < 9; ++j) {
        int c = lane + 32 * j;
        v[j] = (c < cN) ? row[c] : -1e30f;
        m = fmaxf(m, v[j]);
    }
#pragma unroll
    for (int o = 16; o; o >>= 1) m = fmaxf(m, __shfl_xor_sync(0xffffffffu, m, o));
    float s = 0.f;
#pragma unroll
    for (int j = 0; j < 9; ++j) { v[j] = expf(v[j] - m); s += v[j]; }
#pragma unroll
    for (int o = 16; o; o >>= 1) s += __shfl_xor_sync(0xffffffffu, s, o);
    float inv = 1.f / s;
#pragma unroll
    for (int j = 0; j < 9; ++j) {
        int c = lane + 32 * j;
        if (c < cN) row[c] = roundtf(v[j] * inv);
    }
}

// ---------------- launch -----------------------------------------------------
static inline void launch_gemm(const GArgs& a, int batch)
{
    dim3 grid((a.Nv + TN_ - 1) / TN_, (a.M + TM_ - 1) / TM_, batch);
    gemm_tc<<<grid, 256, SMEM_BYTES>>>(a);
}

extern "C" void kernel_launch(void* const* d_in, const int* in_sizes, int n_in,
                              void* d_out, int out_size)
{
    const float* features = (const float*)d_in[0];
    const float* s1 = (const float*)d_in[1];
    const float* s2 = (const float*)d_in[2];
    const float* s3 = (const float*)d_in[3];
    const float* s4 = (const float*)d_in[4];
    const float* wq_b = (const float*)d_in[5];
    const float* wk_b = (const float*)d_in[6];
    const float* wv_b = (const float*)d_in[7];
    const float* wq   = (const float*)d_in[8];
    const float* wk   = (const float*)d_in[9];
    const float* wv   = (const float*)d_in[10];
    float* out = (float*)d_out;

    cudaFuncSetAttribute(gemm_tc, cudaFuncAttributeMaxDynamicSharedMemorySize, SMEM_BYTES);

    float *WT, *F, *S, *Q, *KV, *Vt, *P, *MS, *K2, *V2, *V2t, *P2;
    cudaGetSymbolAddress((void**)&WT,  g_WT);
    cudaGetSymbolAddress((void**)&F,   g_F);
    cudaGetSymbolAddress((void**)&S,   g_S);
    cudaGetSymbolAddress((void**)&Q,   g_q);
    cudaGetSymbolAddress((void**)&KV,  g_KV);
    cudaGetSymbolAddress((void**)&Vt,  g_Vt);
    cudaGetSymbolAddress((void**)&P,   g_P);
    cudaGetSymbolAddress((void**)&MS,  g_ms);
    cudaGetSymbolAddress((void**)&K2,  g_K2);
    cudaGetSymbolAddress((void**)&V2,  g_V2);
    cudaGetSymbolAddress((void**)&V2t, g_V2t);
    cudaGetSymbolAddress((void**)&P2,  g_P2);

    float* Kb = KV;
    float* Vb = KV + (size_t)cB * SNE;

    // 0) round inputs + transpose/round weights
    convert_inputs<<<dim3(512, 1, 5), 256>>>(features, s1, s2, s3, s4);
    transpose_w<<<dim3(32, 32, 15), dim3(32, 8)>>>(wq_b, wk_b, wv_b, wq, wk, wv);

    // 1) q projections: branches 0..3 batched (z via zh: per-z offsets in Hi)
    launch_gemm({F, WT, Q, cN, 1024, 1024, 1024,
                 0, 0, 0, (long)MM, 0, (long)NE, 0, 1, 1.f}, 4);
    launch_gemm({F, WT + 12 * MM, Q + 4 * NE, cN, 1024, 1024, 1024,
                 0, 0, 0, 0, 0, 0, 0, 1, 1.f}, 1);

    // 2) stage-1 K/V projections: one batched launch, z = kv*4 + br
    launch_gemm({S, WT + 4 * MM, KV, TNK, 1024, 1024, 1024,
                 2, 0, (long)SNE,
                 (long)(4 * MM), (long)MM,
                 (long)(cB * SNE), (long)SNE, 1, 1.f}, 8);

    // 3) stage-1 scores -> P[b][n][t][m], scaled (softmax rewrites; no round)
    launch_gemm({Q, Kb, P, cN, cN, 1024, (long)TNK,
                 5, (long)NE, 0,
                 (long)SNE, (long)cN * cE,
                 (long)cN * TNK, (long)cN, 0, cScale}, cB * cS);

    // 4) softmax over 34304 rows of 268 (rounds output)
    {
        int rows = cB * cN * cS;
        softmax_kernel<<<(rows + 7) / 8, 256>>>(P, rows);
    }

    // 5) transpose V -> Vt[b][e][tm] (rounds)
    transpose_g<<<dim3(32, TNK / 32, 4), dim3(32, 8)>>>(
        Vb, Vt, TNK, 1024, SNE, (size_t)cE * TNK);

    // 6) branch outputs: ms[b] = P[b] (268 x 8576) * Vt[b]^T  (K=8576, round)
    launch_gemm({P, Vt, MS, cN, 1024, TNK, 1024,
                 0, (long)cN * TNK, 0, (long)cE * TNK, 0, (long)NE, 0, 1, 1.f}, 4);

    // 7) stage-2 K/V projections (round)
    launch_gemm({MS, WT + 13 * MM, K2, 4 * cN, 1024, 1024, 1024,
                 0, 0, 0, 0, 0, 0, 0, 1, 1.f}, 1);
    launch_gemm({MS, WT + 14 * MM, V2, 4 * cN, 1024, 1024, 1024,
                 0, 0, 0, 0, 0, 0, 0, 1, 1.f}, 1);

    // 8) stage-2 scores -> P2[n][t][m] (softmax rewrites)
    launch_gemm({Q + 4 * NE, K2, P2, cN, cN, 1024, (long)4 * cN,
                 0, 0, 0, (long)cN * cE, 0, (long)cN, 0, 0, cScale}, 4);

    // 9) softmax over 1072 rows (rounds)
    softmax_kernel<<<(4 * cN + 7) / 8, 256>>>(P2, 4 * cN);

    // 10) transpose V2 -> V2t[e][tm] (rounds)
    transpose_g<<<dim3(32, (4 * cN + 31) / 32, 1), dim3(32, 8)>>>(
        V2, V2t, 4 * cN, 1024, 0, 0);

    // 11) final: out = P2 (268 x 1072) * V2t^T  (K=1072, NO round)
    launch_gemm({P2, V2t, out, cN, 1024, 4 * cN, 1024,
                 0, 0, 0, 0, 0, 0, 0, 0, 1.f}, 1);
}

// round 7
// speedup vs baseline: 6.4574x; 1.9357x over previous
#include <cuda_runtime.h>
#include <stdint.h>

// ---------------- problem constants ----------------------------------------
constexpr int cN = 268, cS = 32, cE = 1024, cB = 4;
constexpr float cScale = 0.03125f;           // 1/sqrt(1024)
constexpr size_t MM  = 1024ull * 1024ull;
constexpr int   TNK  = cS * cN;              // 8576
constexpr size_t NE  = (size_t)cN * cE;      // 274432
constexpr size_t SNE = (size_t)TNK * cE;     // 8781824
constexpr int   KSPL = 4;                    // split-K factor for U
constexpr int   KCH  = TNK / KSPL;           // 2144

// ---------------- scratch (device globals) ----------------------------------
__device__ __align__(1024) float g_Wr [10 * MM];   // rounded: wq_b(0-3), wq(4), wk_b(5-8), wk(9)
__device__ __align__(1024) float g_WvT[5 * MM];    // transposed+rounded: wv_b(0-3), wv(4)
__device__ __align__(1024) float g_G  [5 * MM];    // folded G = wq*wk^T per branch + stage2
__device__ __align__(1024) float g_F  [cN * cE];   // rounded features
__device__ __align__(1024) float g_S  [4 * SNE];   // rounded snapshots [b][tm][e]
__device__ __align__(1024) float g_St [4 * SNE];   // transposed rounded snapshots [b][e][tm]
__device__ __align__(1024) float g_qh [5 * NE];    // q-tilde per branch + stage2
__device__ __align__(1024) float g_P  [(size_t)cB * cN * TNK];  // probs [b][n][t*m]
__device__ __align__(1024) float g_UP [16 * NE];   // U split-K partials [b][ks][n][e]
__device__ __align__(1024) float g_U  [4 * NE];    // U reduced+rounded
__device__ __align__(1024) float g_ms [4 * NE];    // branch outputs (rounded)
__device__ __align__(1024) float g_MST[(size_t)cE * 4 * cN];    // ms^T [e][tm2]
__device__ __align__(1024) float g_P2 [(size_t)cN * 4 * cN];    // stage2 probs [n][t*m]
__device__ __align__(1024) float g_U2 [NE];        // stage2 U (rounded)

// ---------------- PTX helpers -----------------------------------------------
__device__ __forceinline__ uint32_t smem_u32(const void* p) {
    uint32_t a;
    asm("{ .reg .u64 t; cvta.to.shared.u64 t, %1; cvt.u32.u64 %0, t; }" : "=r"(a) : "l"(p));
    return a;
}
__device__ __forceinline__ void cp16(uint32_t dst, const void* src, int nbytes) {
    asm volatile("cp.async.cg.shared.global [%0], [%1], 16, %2;"
                 :: "r"(dst), "l"(src), "r"(nbytes));
}
__device__ __forceinline__ float roundtf(float f) {
    uint32_t r;
    asm("cvt.rna.tf32.f32 %0, %1;" : "=r"(r) : "f"(f));
    return __uint_as_float(r);
}
__device__ __forceinline__ void mma_tf32(float* c, const uint32_t* a, const uint32_t* b) {
    asm volatile(
        "mma.sync.aligned.m16n8k8.row.col.f32.tf32.tf32.f32 "
        "{%0,%1,%2,%3}, {%4,%5,%6,%7}, {%8,%9}, {%0,%1,%2,%3};"
        : "+f"(c[0]), "+f"(c[1]), "+f"(c[2]), "+f"(c[3])
        : "r"(a[0]), "r"(a[1]), "r"(a[2]), "r"(a[3]), "r"(b[0]), "r"(b[1]));
}

// ---------------- tf32 mma.sync NT GEMM -------------------------------------
// C[M,Nv] = alpha * A[M,K] * B[Nv,K]^T   (operands pre-rounded to tf32 in gmem)
// batch z: zh = z>>zShift, zl = z & mask; per-operand offset zh*Hi + zl*Lo.
struct GArgs {
    const float* A; const float* B; float* C;
    int M, Nv, K;
    int lda, ldb; long ldc;
    int zShift;
    long aHi, aLo, bHi, bLo, cHi, cLo;
    int roundC;
    float alpha;
};

constexpr int TM_ = 128, TN_ = 128, TK_ = 32;
constexpr int STAGE_F    = TM_ * TK_ + TN_ * TK_;
constexpr int SMEM_BYTES = 2 * STAGE_F * 4;   // 65536

__device__ __forceinline__ int sw_idx(int r, int c) {
    return r * 32 + ((((c >> 2) ^ (r & 7)) << 2) | (c & 3));
}

__global__ void __launch_bounds__(256, 2) gemm_tc(GArgs g)
{
    extern __shared__ __align__(128) float smem[];
    const uint32_t sbase = smem_u32(smem);
    const int tid  = threadIdx.x;
    const int wid  = tid >> 5, lane = tid & 31;
    const int grp  = lane >> 2, tg = lane & 3;

    const int z  = blockIdx.z;
    const long zh = z >> g.zShift;
    const long zl = z & ((1 << g.zShift) - 1);
    const float* A = g.A + zh * g.aHi + zl * g.aLo;
    const float* B = g.B + zh * g.bHi + zl * g.bLo;
    float* C = g.C + zh * g.cHi + zl * g.cLo;

    const int m0 = blockIdx.y * TM_, n0 = blockIdx.x * TN_;
    const int M = g.M, Nv = g.Nv, K = g.K;
    const long lda = g.lda, ldb = g.ldb;
    const int nchunks = (K + TK_ - 1) / TK_;

    const int wrow0 = (wid & 1) * 64;
    const int wcol0 = (wid >> 1) * 32;

    float acc[4][4][4] = {};

    auto load_chunk = [&](int buf, int c) {
        const long k0 = (long)c * TK_;
        const uint32_t sA = sbase + buf * (STAGE_F * 4);
        const uint32_t sB = sA + TM_ * TK_ * 4;
#pragma unroll
        for (int i = 0; i < 4; ++i) {
            int l = tid + i * 256, r = l >> 3, seg = l & 7;
            long grow = m0 + r, gk = k0 + seg * 4;
            bool ok = (grow < M) && (gk < K);
            const float* src = ok ? (A + grow * lda + gk) : A;
            uint32_t off = (uint32_t)(r * 128 + (seg ^ (r & 7)) * 16);
            cp16(sA + off, src, ok ? 16 : 0);
        }
#pragma unroll
        for (int i = 0; i < 4; ++i) {
            int l = tid + i * 256, r = l >> 3, seg = l & 7;
            long grow = n0 + r, gk = k0 + seg * 4;
            bool ok = (grow < Nv) && (gk < K);
            const float* src = ok ? (B + grow * ldb + gk) : B;
            uint32_t off = (uint32_t)(r * 128 + (seg ^ (r & 7)) * 16);
            cp16(sB + off, src, ok ? 16 : 0);
        }
        asm volatile("cp.async.commit_group;");
    };

    load_chunk(0, 0);
    for (int c = 0; c < nchunks; ++c) {
        if (c + 1 < nchunks) {
            load_chunk((c + 1) & 1, c + 1);
            asm volatile("cp.async.wait_group 1;");
        } else {
            asm volatile("cp.async.wait_group 0;");
        }
        __syncthreads();

        const float* As = smem + (c & 1) * STAGE_F;
        const float* Bs = As + TM_ * TK_;
        // k-permutation (HW col t <- logical 2t, t+4 <- 2t+1) on both operands:
        // dot-product invariant; fragment pairs become one 8-byte LDS.
#pragma unroll
        for (int ks = 0; ks < 4; ++ks) {
            const int cA = ks * 8 + 2 * tg;
            uint32_t af[4][4], bf[4][2];
#pragma unroll
            for (int mt = 0; mt < 4; ++mt) {
                int r0 = wrow0 + mt * 16 + grp;
                uint2 lo = *(const uint2*)&As[sw_idx(r0,     cA)];
                uint2 hi = *(const uint2*)&As[sw_idx(r0 + 8, cA)];
                af[mt][0] = lo.x; af[mt][1] = hi.x; af[mt][2] = lo.y; af[mt][3] = hi.y;
            }
#pragma unroll
            for (int nt = 0; nt < 4; ++nt) {
                int rn = wcol0 + nt * 8 + grp;
                uint2 bb = *(const uint2*)&Bs[sw_idx(rn, cA)];
                bf[nt][0] = bb.x; bf[nt][1] = bb.y;
            }
#pragma unroll
            for (int mt = 0; mt < 4; ++mt)
#pragma unroll
                for (int nt = 0; nt < 4; ++nt)
                    mma_tf32(acc[mt][nt], af[mt], bf[nt]);
        }
        __syncthreads();
    }

    const float alpha = g.alpha;
    const int rC = g.roundC;
#pragma unroll
    for (int mt = 0; mt < 4; ++mt) {
#pragma unroll
        for (int nt = 0; nt < 4; ++nt) {
            long r0 = m0 + wrow0 + mt * 16 + grp;
            long cc = n0 + wcol0 + nt * 8 + tg * 2;
            if (cc < Nv) {
#pragma unroll
                for (int h = 0; h < 2; ++h) {
                    long rr = r0 + 8 * h;
                    if (rr < M) {
                        float v0 = alpha * acc[mt][nt][2 * h];
                        float v1 = alpha * acc[mt][nt][2 * h + 1];
                        if (rC) { v0 = roundtf(v0); v1 = roundtf(v1); }
                        C[rr * g.ldc + cc]     = v0;
                        C[rr * g.ldc + cc + 1] = v1;
                    }
                }
            }
        }
    }
}

// ---------------- rounding copies --------------------------------------------
__global__ void convert_inputs(const float* __restrict__ f,
                               const float* __restrict__ s1, const float* __restrict__ s2,
                               const float* __restrict__ s3, const float* __restrict__ s4)
{
    const int z = blockIdx.z;
    const float4* src; float4* dst; long n4;
    if (z == 0) {
        src = (const float4*)f; dst = (float4*)g_F; n4 = (long)(cN * cE) / 4;
    } else {
        const float* sp = (z == 1) ? s1 : (z == 2) ? s2 : (z == 3) ? s3 : s4;
        src = (const float4*)sp; dst = (float4*)(g_S + (size_t)(z - 1) * SNE);
        n4 = (long)SNE / 4;
    }
    for (long i = blockIdx.x * (long)blockDim.x + threadIdx.x; i < n4;
         i += (long)gridDim.x * blockDim.x) {
        float4 v = src[i];
        v.x = roundtf(v.x); v.y = roundtf(v.y);
        v.z = roundtf(v.z); v.w = roundtf(v.w);
        dst[i] = v;
    }
}

// rounded copy of wq_b/wq/wk_b/wk into g_Wr (no transpose needed for fold)
__global__ void round_weights(const float* __restrict__ wq_b, const float* __restrict__ wk_b,
                              const float* __restrict__ wq,   const float* __restrict__ wk)
{
    const int z = blockIdx.z;
    const float* src = (z < 4) ? wq_b + (size_t)z * MM
                     : (z == 4) ? wq
                     : (z < 9) ? wk_b + (size_t)(z - 5) * MM
                     : wk;
    const float4* s4 = (const float4*)src;
    float4* d4 = (float4*)(g_Wr + (size_t)z * MM);
    const long n4 = (long)MM / 4;
    for (long i = blockIdx.x * (long)blockDim.x + threadIdx.x; i < n4;
         i += (long)gridDim.x * blockDim.x) {
        float4 v = s4[i];
        v.x = roundtf(v.x); v.y = roundtf(v.y);
        v.z = roundtf(v.z); v.w = roundtf(v.w);
        d4[i] = v;
    }
}

// transpose+round wv_b(0-3)/wv(4) -> g_WvT [f][e]
__global__ void transpose_wv(const float* __restrict__ wv_b, const float* __restrict__ wv)
{
    __shared__ float t[32][33];
    const int z = blockIdx.z;
    const float* src = (z < 4) ? wv_b + (size_t)z * MM : wv;
    float* dst = g_WvT + (size_t)z * MM;
    const int x0 = blockIdx.x * 32, y0 = blockIdx.y * 32;
#pragma unroll
    for (int i = threadIdx.y; i < 32; i += 8)
        t[i][threadIdx.x] = src[(size_t)(y0 + i) * 1024 + x0 + threadIdx.x];
    __syncthreads();
#pragma unroll
    for (int i = threadIdx.y; i < 32; i += 8)
        dst[(size_t)(x0 + i) * 1024 + y0 + threadIdx.x] = roundtf(t[threadIdx.x][i]);
}

// generic transpose+round: dst[c*R + r] = round(src[r*Cc + c])
__global__ void transpose_g(const float* __restrict__ src, float* __restrict__ dst,
                            int R, int Cc)
{
    __shared__ float t[32][33];
    const int x0 = blockIdx.x * 32, y0 = blockIdx.y * 32;
#pragma unroll
    for (int i = threadIdx.y; i < 32; i += 8) {
        int y = y0 + i, x = x0 + threadIdx.x;
        t[i][threadIdx.x] = (y < R && x < Cc) ? src[(size_t)y * Cc + x] : 0.f;
    }
    __syncthreads();
#pragma unroll
    for (int i = threadIdx.y; i < 32; i += 8) {
        int x = x0 + i, y = y0 + threadIdx.x;
        if (x < Cc && y < R) dst[(size_t)x * R + y] = roundtf(t[threadIdx.x][i]);
    }
}

// U[b] = round(sum of 4 split-K partials)
__global__ void reduce4()
{
    const int b = blockIdx.z;
    const float4* p0 = (const float4*)(g_UP + (size_t)(b * 4 + 0) * NE);
    const float4* p1 = (const float4*)(g_UP + (size_t)(b * 4 + 1) * NE);
    const float4* p2 = (const float4*)(g_UP + (size_t)(b * 4 + 2) * NE);
    const float4* p3 = (const float4*)(g_UP + (size_t)(b * 4 + 3) * NE);
    float4* d = (float4*)(g_U + (size_t)b * NE);
    long i = blockIdx.x * (long)blockDim.x + threadIdx.x;
    if (i < (long)NE / 4) {
        float4 a = p0[i], x = p1[i], y = p2[i], w = p3[i];
        float4 r;
        r.x = roundtf(a.x + x.x + y.x + w.x);
        r.y = roundtf(a.y + x.y + y.y + w.y);
        r.z = roundtf(a.z + x.z + y.z + w.z);
        r.w = roundtf(a.w + x.w + y.w + w.w);
        d[i] = r;
    }
}

// ---------------- softmax (warp per row of 268; rounds output) ---------------
__global__ __launch_bounds__(256) void softmax_kernel(float* __restrict__ base, int rows)
{
    int w = (blockIdx.x * blockDim.x + threadIdx.x) >> 5;
    int lane = threadIdx.x & 31;
    if (w >= rows) return;
    float* row = base + (size_t)w * cN;

    float v[9];
    float m = -1e30f;
#pragma unroll
    for (int j = 0; j < 9; ++j) {
        int c = lane + 32 * j;
        v[j] = (c < cN) ? row[c] : -1e30f;
        m = fmaxf(m, v[j]);
    }
#pragma unroll
    for (int o = 16; o; o >>= 1) m = fmaxf(m, __shfl_xor_sync(0xffffffffu, m, o));
    float s = 0.f;
#pragma unroll
    for (int j = 0; j < 9; ++j) { v[j] = expf(v[j] - m); s += v[j]; }
#pragma unroll
    for (int o = 16; o; o >>= 1) s += __shfl_xor_sync(0xffffffffu, s, o);
    float inv = 1.f / s;
#pragma unroll
    for (int j = 0; j < 9; ++j) {
        int c = lane + 32 * j;
        if (c < cN) row[c] = roundtf(v[j] * inv);
    }
}

// ---------------- launch -----------------------------------------------------
static inline void launch_gemm(const GArgs& a, int batch)
{
    dim3 grid((a.Nv + TN_ - 1) / TN_, (a.M + TM_ - 1) / TM_, batch);
    gemm_tc<<<grid, 256, SMEM_BYTES>>>(a);
}

extern "C" void kernel_launch(void* const* d_in, const int* in_sizes, int n_in,
                              void* d_out, int out_size)
{
    const float* features = (const float*)d_in[0];
    const float* s1 = (const float*)d_in[1];
    const float* s2 = (const float*)d_in[2];
    const float* s3 = (const float*)d_in[3];
    const float* s4 = (const float*)d_in[4];
    const float* wq_b = (const float*)d_in[5];
    const float* wk_b = (const float*)d_in[6];
    const float* wv_b = (const float*)d_in[7];
    const float* wq   = (const float*)d_in[8];
    const float* wk   = (const float*)d_in[9];
    const float* wv   = (const float*)d_in[10];
    float* out = (float*)d_out;

    cudaFuncSetAttribute(gemm_tc, cudaFuncAttributeMaxDynamicSharedMemorySize, SMEM_BYTES);

    float *Wr, *WvT, *G, *F, *S, *St, *QH, *P, *UP, *U, *MSp, *MST, *P2, *U2;
    cudaGetSymbolAddress((void**)&Wr,  g_Wr);
    cudaGetSymbolAddress((void**)&WvT, g_WvT);
    cudaGetSymbolAddress((void**)&G,   g_G);
    cudaGetSymbolAddress((void**)&F,   g_F);
    cudaGetSymbolAddress((void**)&S,   g_S);
    cudaGetSymbolAddress((void**)&St,  g_St);
    cudaGetSymbolAddress((void**)&QH,  g_qh);
    cudaGetSymbolAddress((void**)&P,   g_P);
    cudaGetSymbolAddress((void**)&UP,  g_UP);
    cudaGetSymbolAddress((void**)&U,   g_U);
    cudaGetSymbolAddress((void**)&MSp, g_ms);
    cudaGetSymbolAddress((void**)&MST, g_MST);
    cudaGetSymbolAddress((void**)&P2,  g_P2);
    cudaGetSymbolAddress((void**)&U2,  g_U2);

    const float* s_in[4] = { s1, s2, s3, s4 };

    // 0) round inputs / weights; transpose wv and s
    convert_inputs<<<dim3(512, 1, 5), 256>>>(features, s1, s2, s3, s4);
    round_weights<<<dim3(256, 1, 10), 256>>>(wq_b, wk_b, wq, wk);
    transpose_wv<<<dim3(32, 32, 5), dim3(32, 8)>>>(wv_b, wv);
    for (int b = 0; b < 4; ++b)
        transpose_g<<<dim3(32, TNK / 32, 1), dim3(32, 8)>>>(
            s_in[b], St + (size_t)b * SNE, TNK, 1024);

    // 1) fold G[z] = wq_z * wk_z^T  (z=0..3 branches, z=4 stage2)
    launch_gemm({Wr, Wr + 5 * MM, G, 1024, 1024, 1024, 1024, 1024, 1024,
                 0, (long)MM, 0, (long)MM, 0, (long)MM, 0, 1, 1.f}, 5);

    // 2) q-tilde[z] = F * G[z]^T? No: q~ = F @ G -> NT with B = G^T... G built as
    //    G[g][e] row-major with K=g? Fold produced C=G with rows g, cols e.
    //    q~[n,e] = sum_g F[n,g] G[g,e]: NT needs B[e][g] = G^T. Instead build
    //    G^T directly: fold with A=wk, B=wq gives Gt[e][g]. (swap operands)
    //    -- handled above by ordering: we actually need Gt; relaunch form:
    //    (the call in step 1 computes with A=wq rows g; we need B-side = wq)
    // NOTE: step 1 computes G[g][e]; we need Gt[e][g] for the NT q~ GEMM.
    //       Recompute as Gt = wk * wq^T (A=wk rows e, B=wq rows g) — same cost.
    launch_gemm({Wr + 5 * MM, Wr, G, 1024, 1024, 1024, 1024, 1024, 1024,
                 0, (long)MM, 0, (long)MM, 0, (long)MM, 0, 1, 1.f}, 5);

    // q~[z] = F @ Gt[z]^T  (NT: B rows = e of Gt -> B[e][g], K = g)  [268x1024]
    launch_gemm({F, G, QH, cN, 1024, 1024, 1024, 1024, 1024,
                 0, 0, 0, (long)MM, 0, (long)NE, 0, 1, 1.f}, 5);

    // 3) stage-1 scores: P[b][n][tm] = scale * q~_b @ s_b^T  (NT, B rows = tm)
    launch_gemm({QH, S, P, cN, TNK, 1024, 1024, 1024, (long)TNK,
                 0, (long)NE, 0, (long)SNE, 0, (long)cN * TNK, 0, 0, cScale}, 4);

    // 4) softmax over 34304 segments of 268
    {
        int rows = cB * cN * cS;
        softmax_kernel<<<(rows + 7) / 8, 256>>>(P, rows);
    }

    // 5) U partials: z = b*4+ks;  U_part = P_b[:, ks*2144:+2144] @ St_b[:, same]^T
    launch_gemm({P, St, UP, cN, 1024, KCH, TNK, TNK, 1024,
                 2, (long)cN * TNK, (long)KCH, (long)SNE, (long)KCH,
                 (long)(4 * NE), (long)NE, 0, 1.f}, 16);
    reduce4<<<dim3((int)(NE / 4 / 256), 1, 4), 256>>>();

    // 6) ms_b = U_b @ wv_b  (NT with B = WvT[b] = wv_b^T rows f)  [268x1024]
    launch_gemm({U, WvT, MSp, cN, 1024, 1024, 1024, 1024, 1024,
                 0, (long)NE, 0, (long)MM, 0, (long)NE, 0, 1, 1.f}, 4);

    // 7) stage-2 scores: P2[n][tm2] = scale * q~2 @ ms^T (ms as 1072 x 1024)
    launch_gemm({QH + 4 * NE, MSp, P2, cN, 4 * cN, 1024, 1024, 1024, (long)(4 * cN),
                 0, 0, 0, 0, 0, 0, 0, 0, cScale}, 1);
    softmax_kernel<<<(4 * cN + 7) / 8, 256>>>(P2, 4 * cN);

    // 8) U2 = P2 @ ms  -> need ms^T [1024][1072]
    transpose_g<<<dim3(32, (4 * cN + 31) / 32, 1), dim3(32, 8)>>>(MSp, MST, 4 * cN, 1024);
    launch_gemm({P2, MST, U2, cN, 1024, 4 * cN, 4 * cN, 4 * cN, 1024,
                 0, 0, 0, 0, 0, 0, 0, 1, 1.f}, 1);

    // 9) out = U2 @ wv  (NT with B = WvT[4] = wv^T)
    launch_gemm({U2, WvT + 4 * MM, out, cN, 1024, 1024, 1024, 1024, 1024,
                 0, 0, 0, 0, 0, 0, 0, 0, 1.f}, 1);
}

// round 8
// speedup vs baseline: 7.6383x; 1.1829x over previous
#include <cuda_runtime.h>
#include <stdint.h>

// ---------------- problem constants ----------------------------------------
constexpr int cN = 268, cS = 32, cE = 1024, cB = 4;
constexpr float cScale = 0.03125f;           // 1/sqrt(1024)
constexpr size_t MM  = 1024ull * 1024ull;
constexpr int   TNK  = cS * cN;              // 8576
constexpr size_t NE  = (size_t)cN * cE;      // 274432
constexpr size_t SNE = (size_t)TNK * cE;     // 8781824
constexpr int   KSPL = 4;                    // split-K factor for U
constexpr int   KCH  = TNK / KSPL;           // 2144

// ---------------- scratch (device globals) ----------------------------------
__device__ __align__(1024) float g_Wr [10 * MM];   // rounded: wq_b(0-3), wq(4), wk_b(5-8), wk(9)
__device__ __align__(1024) float g_WvT[5 * MM];    // transposed+rounded: wv_b(0-3), wv(4)
__device__ __align__(1024) float g_G  [5 * MM];    // Gt = wk*wq^T per branch + stage2
__device__ __align__(1024) float g_F  [cN * cE];   // rounded features
__device__ __align__(1024) float g_S  [4 * SNE];   // rounded snapshots [b][tm][e]
__device__ __align__(1024) float g_St [4 * SNE];   // rounded transposed snapshots [b][e][tm]
__device__ __align__(1024) float g_qh [5 * NE];    // q-tilde per branch + stage2
__device__ __align__(1024) float g_P  [(size_t)cB * cN * TNK];  // probs [b][n][t*m]
__device__ __align__(1024) float g_UP [16 * NE];   // U split-K partials [b][ks][n][e]
__device__ __align__(1024) float g_U  [4 * NE];    // U reduced+rounded
__device__ __align__(1024) float g_ms [4 * NE];    // branch outputs (rounded)
__device__ __align__(1024) float g_MST[(size_t)cE * 4 * cN];    // ms^T [e][tm2]
__device__ __align__(1024) float g_P2 [(size_t)cN * 4 * cN];    // stage2 probs [n][t*m]
__device__ __align__(1024) float g_U2 [NE];        // stage2 U (rounded)

// ---------------- PTX helpers -----------------------------------------------
__device__ __forceinline__ uint32_t smem_u32(const void* p) {
    uint32_t a;
    asm("{ .reg .u64 t; cvta.to.shared.u64 t, %1; cvt.u32.u64 %0, t; }" : "=r"(a) : "l"(p));
    return a;
}
__device__ __forceinline__ void cp16(uint32_t dst, const void* src, int nbytes) {
    asm volatile("cp.async.cg.shared.global [%0], [%1], 16, %2;"
                 :: "r"(dst), "l"(src), "r"(nbytes));
}
__device__ __forceinline__ float roundtf(float f) {
    uint32_t r;
    asm("cvt.rna.tf32.f32 %0, %1;" : "=r"(r) : "f"(f));
    return __uint_as_float(r);
}
__device__ __forceinline__ void mma_tf32(float* c, const uint32_t* a, const uint32_t* b) {
    asm volatile(
        "mma.sync.aligned.m16n8k8.row.col.f32.tf32.tf32.f32 "
        "{%0,%1,%2,%3}, {%4,%5,%6,%7}, {%8,%9}, {%0,%1,%2,%3};"
        : "+f"(c[0]), "+f"(c[1]), "+f"(c[2]), "+f"(c[3])
        : "r"(a[0]), "r"(a[1]), "r"(a[2]), "r"(a[3]), "r"(b[0]), "r"(b[1]));
}

// ---------------- tf32 mma.sync NT GEMM (3-stage cp.async pipeline) ----------
// C[M,Nv] = alpha * A[M,K] * B[Nv,K]^T   (operands pre-rounded to tf32)
// batch z: zh = z>>zShift, zl = z & mask; per-operand offset zh*Hi + zl*Lo.
struct GArgs {
    const float* A; const float* B; float* C;
    int M, Nv, K;
    int lda, ldb; long ldc;
    int zShift;
    long aHi, aLo, bHi, bLo, cHi, cLo;
    int roundC;
    float alpha;
};

constexpr int TM_ = 128, TN_ = 128, TK_ = 32;
constexpr int STAGE_F    = TM_ * TK_ + TN_ * TK_;   // 8192 floats
constexpr int NSTAGE     = 3;
constexpr int SMEM_BYTES = NSTAGE * STAGE_F * 4;    // 98304

__device__ __forceinline__ int sw_idx(int r, int c) {
    return r * 32 + ((((c >> 2) ^ (r & 7)) << 2) | (c & 3));
}

__global__ void __launch_bounds__(256, 2) gemm_tc(GArgs g)
{
    extern __shared__ __align__(128) float smem[];
    const uint32_t sbase = smem_u32(smem);
    const int tid  = threadIdx.x;
    const int wid  = tid >> 5, lane = tid & 31;
    const int grp  = lane >> 2, tg = lane & 3;

    const int z  = blockIdx.z;
    const long zh = z >> g.zShift;
    const long zl = z & ((1 << g.zShift) - 1);
    const float* A = g.A + zh * g.aHi + zl * g.aLo;
    const float* B = g.B + zh * g.bHi + zl * g.bLo;
    float* C = g.C + zh * g.cHi + zl * g.cLo;

    const int m0 = blockIdx.y * TM_, n0 = blockIdx.x * TN_;
    const int M = g.M, Nv = g.Nv, K = g.K;
    const long lda = g.lda, ldb = g.ldb;
    const int nchunks = (K + TK_ - 1) / TK_;

    const int wrow0 = (wid & 1) * 64;
    const int wcol0 = (wid >> 1) * 32;

    float acc[4][4][4] = {};

    auto load_chunk = [&](int buf, int c) {
        const long k0 = (long)c * TK_;
        const uint32_t sA = sbase + buf * (STAGE_F * 4);
        const uint32_t sB = sA + TM_ * TK_ * 4;
#pragma unroll
        for (int i = 0; i < 4; ++i) {
            int l = tid + i * 256, r = l >> 3, seg = l & 7;
            long grow = m0 + r, gk = k0 + seg * 4;
            bool ok = (grow < M) && (gk < K);
            const float* src = ok ? (A + grow * lda + gk) : A;
            uint32_t off = (uint32_t)(r * 128 + (seg ^ (r & 7)) * 16);
            cp16(sA + off, src, ok ? 16 : 0);
        }
#pragma unroll
        for (int i = 0; i < 4; ++i) {
            int l = tid + i * 256, r = l >> 3, seg = l & 7;
            long grow = n0 + r, gk = k0 + seg * 4;
            bool ok = (grow < Nv) && (gk < K);
            const float* src = ok ? (B + grow * ldb + gk) : B;
            uint32_t off = (uint32_t)(r * 128 + (seg ^ (r & 7)) * 16);
            cp16(sB + off, src, ok ? 16 : 0);
        }
        asm volatile("cp.async.commit_group;");
    };

    // prologue: fill 2 stages
    load_chunk(0, 0);
    if (nchunks > 1) load_chunk(1, 1);

    int buf = 0;
    for (int c = 0; c < nchunks; ++c) {
        if (c + 2 < nchunks) {
            int nb = buf + 2; if (nb >= NSTAGE) nb -= NSTAGE;
            load_chunk(nb, c + 2);
            asm volatile("cp.async.wait_group 2;");
        } else if (c + 1 < nchunks) {
            asm volatile("cp.async.wait_group 1;");
        } else {
            asm volatile("cp.async.wait_group 0;");
        }
        __syncthreads();

        const float* As = smem + buf * STAGE_F;
        const float* Bs = As + TM_ * TK_;
        // k-permutation (HW col t <- logical 2t, t+4 <- 2t+1) on both operands:
        // dot-product invariant; fragment pairs become one 8-byte LDS.
#pragma unroll
        for (int ks = 0; ks < 4; ++ks) {
            const int cA = ks * 8 + 2 * tg;
            uint32_t af[4][4], bf[4][2];
#pragma unroll
            for (int mt = 0; mt < 4; ++mt) {
                int r0 = wrow0 + mt * 16 + grp;
                uint2 lo = *(const uint2*)&As[sw_idx(r0,     cA)];
                uint2 hi = *(const uint2*)&As[sw_idx(r0 + 8, cA)];
                af[mt][0] = lo.x; af[mt][1] = hi.x; af[mt][2] = lo.y; af[mt][3] = hi.y;
            }
#pragma unroll
            for (int nt = 0; nt < 4; ++nt) {
                int rn = wcol0 + nt * 8 + grp;
                uint2 bb = *(const uint2*)&Bs[sw_idx(rn, cA)];
                bf[nt][0] = bb.x; bf[nt][1] = bb.y;
            }
#pragma unroll
            for (int mt = 0; mt < 4; ++mt)
#pragma unroll
                for (int nt = 0; nt < 4; ++nt)
                    mma_tf32(acc[mt][nt], af[mt], bf[nt]);
        }
        __syncthreads();
        if (++buf == NSTAGE) buf = 0;
    }

    const float alpha = g.alpha;
    const int rC = g.roundC;
#pragma unroll
    for (int mt = 0; mt < 4; ++mt) {
#pragma unroll
        for (int nt = 0; nt < 4; ++nt) {
            long r0 = m0 + wrow0 + mt * 16 + grp;
            long cc = n0 + wcol0 + nt * 8 + tg * 2;
            if (cc < Nv) {
#pragma unroll
                for (int h = 0; h < 2; ++h) {
                    long rr = r0 + 8 * h;
                    if (rr < M) {
                        float v0 = alpha * acc[mt][nt][2 * h];
                        float v1 = alpha * acc[mt][nt][2 * h + 1];
                        if (rC) { v0 = roundtf(v0); v1 = roundtf(v1); }
                        C[rr * g.ldc + cc]     = v0;
                        C[rr * g.ldc + cc + 1] = v1;
                    }
                }
            }
        }
    }
}

// ---------------- fused s prep: round -> g_S, round+transpose -> g_St --------
__global__ void prep_s(const float* __restrict__ s1, const float* __restrict__ s2,
                       const float* __restrict__ s3, const float* __restrict__ s4)
{
    __shared__ float t[32][33];
    const int b = blockIdx.z;
    const float* src = (b == 0) ? s1 : (b == 1) ? s2 : (b == 2) ? s3 : s4;
    float* dstS  = g_S  + (size_t)b * SNE;
    float* dstSt = g_St + (size_t)b * SNE;
    const int x0 = blockIdx.x * 32;   // e-dim (1024)
    const int y0 = blockIdx.y * 32;   // tm-dim (8576)
#pragma unroll
    for (int i = threadIdx.y; i < 32; i += 8) {
        float v = roundtf(src[(size_t)(y0 + i) * cE + x0 + threadIdx.x]);
        t[i][threadIdx.x] = v;
        dstS[(size_t)(y0 + i) * cE + x0 + threadIdx.x] = v;
    }
    __syncthreads();
#pragma unroll
    for (int i = threadIdx.y; i < 32; i += 8)
        dstSt[(size_t)(x0 + i) * TNK + y0 + threadIdx.x] = t[threadIdx.x][i];
}

// ---------------- rounding copies --------------------------------------------
__global__ void convert_F(const float* __restrict__ f)
{
    long i = blockIdx.x * (long)blockDim.x + threadIdx.x;
    if (i < (long)(cN * cE) / 4) {
        float4 v = ((const float4*)f)[i];
        v.x = roundtf(v.x); v.y = roundtf(v.y);
        v.z = roundtf(v.z); v.w = roundtf(v.w);
        ((float4*)g_F)[i] = v;
    }
}

__global__ void round_weights(const float* __restrict__ wq_b, const float* __restrict__ wk_b,
                              const float* __restrict__ wq,   const float* __restrict__ wk)
{
    const int z = blockIdx.z;
    const float* src = (z < 4) ? wq_b + (size_t)z * MM
                     : (z == 4) ? wq
                     : (z < 9) ? wk_b + (size_t)(z - 5) * MM
                     : wk;
    const float4* s4 = (const float4*)src;
    float4* d4 = (float4*)(g_Wr + (size_t)z * MM);
    const long n4 = (long)MM / 4;
    for (long i = blockIdx.x * (long)blockDim.x + threadIdx.x; i < n4;
         i += (long)gridDim.x * blockDim.x) {
        float4 v = s4[i];
        v.x = roundtf(v.x); v.y = roundtf(v.y);
        v.z = roundtf(v.z); v.w = roundtf(v.w);
        d4[i] = v;
    }
}

__global__ void transpose_wv(const float* __restrict__ wv_b, const float* __restrict__ wv)
{
    __shared__ float t[32][33];
    const int z = blockIdx.z;
    const float* src = (z < 4) ? wv_b + (size_t)z * MM : wv;
    float* dst = g_WvT + (size_t)z * MM;
    const int x0 = blockIdx.x * 32, y0 = blockIdx.y * 32;
#pragma unroll
    for (int i = threadIdx.y; i < 32; i += 8)
        t[i][threadIdx.x] = src[(size_t)(y0 + i) * 1024 + x0 + threadIdx.x];
    __syncthreads();
#pragma unroll
    for (int i = threadIdx.y; i < 32; i += 8)
        dst[(size_t)(x0 + i) * 1024 + y0 + threadIdx.x] = roundtf(t[threadIdx.x][i]);
}

// generic transpose+round: dst[c*R + r] = round(src[r*Cc + c])
__global__ void transpose_g(const float* __restrict__ src, float* __restrict__ dst,
                            int R, int Cc)
{
    __shared__ float t[32][33];
    const int x0 = blockIdx.x * 32, y0 = blockIdx.y * 32;
#pragma unroll
    for (int i = threadIdx.y; i < 32; i += 8) {
        int y = y0 + i, x = x0 + threadIdx.x;
        t[i][threadIdx.x] = (y < R && x < Cc) ? src[(size_t)y * Cc + x] : 0.f;
    }
    __syncthreads();
#pragma unroll
    for (int i = threadIdx.y; i < 32; i += 8) {
        int x = x0 + i, y = y0 + threadIdx.x;
        if (x < Cc && y < R) dst[(size_t)x * R + y] = roundtf(t[threadIdx.x][i]);
    }
}

// U[b] = round(sum of 4 split-K partials)
__global__ void reduce4()
{
    const int b = blockIdx.z;
    const float4* p0 = (const float4*)(g_UP + (size_t)(b * 4 + 0) * NE);
    const float4* p1 = (const float4*)(g_UP + (size_t)(b * 4 + 1) * NE);
    const float4* p2 = (const float4*)(g_UP + (size_t)(b * 4 + 2) * NE);
    const float4* p3 = (const float4*)(g_UP + (size_t)(b * 4 + 3) * NE);
    float4* d = (float4*)(g_U + (size_t)b * NE);
    long i = blockIdx.x * (long)blockDim.x + threadIdx.x;
    if (i < (long)NE / 4) {
        float4 a = p0[i], x = p1[i], y = p2[i], w = p3[i];
        float4 r;
        r.x = roundtf(a.x + x.x + y.x + w.x);
        r.y = roundtf(a.y + x.y + y.y + w.y);
        r.z = roundtf(a.z + x.z + y.z + w.z);
        r.w = roundtf(a.w + x.w + y.w + w.w);
        d[i] = r;
    }
}

// ---------------- softmax (warp per row of 268; rounds output) ---------------
__global__ __launch_bounds__(256) void softmax_kernel(float* __restrict__ base, int rows)
{
    int w = (blockIdx.x * blockDim.x + threadIdx.x) >> 5;
    int lane = threadIdx.x & 31;
    if (w >= rows) return;
    float* row = base + (size_t)w * cN;

    float v[9];
    float m = -1e30f;
#pragma unroll
    for (int j = 0; j < 9; ++j) {
        int c = lane + 32 * j;
        v[j] = (c < cN) ? row[c] : -1e30f;
        m = fmaxf(m, v[j]);
    }
#pragma unroll
    for (int o = 16; o; o >>= 1) m = fmaxf(m, __shfl_xor_sync(0xffffffffu, m, o));
    float s = 0.f;
#pragma unroll
    for (int j = 0; j < 9; ++j) { v[j] = expf(v[j] - m); s += v[j]; }
#pragma unroll
    for (int o = 16; o; o >>= 1) s += __shfl_xor_sync(0xffffffffu, s, o);
    float inv = 1.f / s;
#pragma unroll
    for (int j = 0; j < 9; ++j) {
        int c = lane + 32 * j;
        if (c < cN) row[c] = roundtf(v[j] * inv);
    }
}

// ---------------- launch -----------------------------------------------------
static inline void launch_gemm(const GArgs& a, int batch)
{
    dim3 grid((a.Nv + TN_ - 1) / TN_, (a.M + TM_ - 1) / TM_, batch);
    gemm_tc<<<grid, 256, SMEM_BYTES>>>(a);
}

extern "C" void kernel_launch(void* const* d_in, const int* in_sizes, int n_in,
                              void* d_out, int out_size)
{
    const float* features = (const float*)d_in[0];
    const float* s1 = (const float*)d_in[1];
    const float* s2 = (const float*)d_in[2];
    const float* s3 = (const float*)d_in[3];
    const float* s4 = (const float*)d_in[4];
    const float* wq_b = (const float*)d_in[5];
    const float* wk_b = (const float*)d_in[6];
    const float* wv_b = (const float*)d_in[7];
    const float* wq   = (const float*)d_in[8];
    const float* wk   = (const float*)d_in[9];
    const float* wv   = (const float*)d_in[10];
    float* out = (float*)d_out;

    cudaFuncSetAttribute(gemm_tc, cudaFuncAttributeMaxDynamicSharedMemorySize, SMEM_BYTES);

    float *Wr, *WvT, *G, *F, *S, *St, *QH, *P, *UP, *U, *MSp, *MST, *P2, *U2;
    cudaGetSymbolAddress((void**)&Wr,  g_Wr);
    cudaGetSymbolAddress((void**)&WvT, g_WvT);
    cudaGetSymbolAddress((void**)&G,   g_G);
    cudaGetSymbolAddress((void**)&F,   g_F);
    cudaGetSymbolAddress((void**)&S,   g_S);
    cudaGetSymbolAddress((void**)&St,  g_St);
    cudaGetSymbolAddress((void**)&QH,  g_qh);
    cudaGetSymbolAddress((void**)&P,   g_P);
    cudaGetSymbolAddress((void**)&UP,  g_UP);
    cudaGetSymbolAddress((void**)&U,   g_U);
    cudaGetSymbolAddress((void**)&MSp, g_ms);
    cudaGetSymbolAddress((void**)&MST, g_MST);
    cudaGetSymbolAddress((void**)&P2,  g_P2);
    cudaGetSymbolAddress((void**)&U2,  g_U2);

    // 0) prep: round F; round+transpose s (single pass); round weights; wv^T
    convert_F<<<(cN * cE / 4 + 255) / 256, 256>>>(features);
    prep_s<<<dim3(32, TNK / 32, 4), dim3(32, 8)>>>(s1, s2, s3, s4);
    round_weights<<<dim3(256, 1, 10), 256>>>(wq_b, wk_b, wq, wk);
    transpose_wv<<<dim3(32, 32, 5), dim3(32, 8)>>>(wv_b, wv);

    // 1) fold Gt[z] = wk_z * wq_z^T  (z=0..3 branches, z=4 stage2)
    launch_gemm({Wr + 5 * MM, Wr, G, 1024, 1024, 1024, 1024, 1024, 1024,
                 0, (long)MM, 0, (long)MM, 0, (long)MM, 0, 1, 1.f}, 5);

    // 2) q~[z] = F @ Gt[z]^T  (NT: B rows = e of Gt)  [268x1024]
    launch_gemm({F, G, QH, cN, 1024, 1024, 1024, 1024, 1024,
                 0, 0, 0, (long)MM, 0, (long)NE, 0, 1, 1.f}, 5);

    // 3) stage-1 scores: P[b][n][tm] = scale * q~_b @ s_b^T  (NT, B rows = tm)
    launch_gemm({QH, S, P, cN, TNK, 1024, 1024, 1024, (long)TNK,
                 0, (long)NE, 0, (long)SNE, 0, (long)cN * TNK, 0, 0, cScale}, 4);

    // 4) softmax over 34304 segments of 268
    {
        int rows = cB * cN * cS;
        softmax_kernel<<<(rows + 7) / 8, 256>>>(P, rows);
    }

    // 5) U partials: z = b*4+ks;  U_part = P_b[:, ks*KCH:+KCH] @ St_b[:, same]^T
    launch_gemm({P, St, UP, cN, 1024, KCH, TNK, TNK, 1024,
                 2, (long)cN * TNK, (long)KCH, (long)SNE, (long)KCH,
                 (long)(4 * NE), (long)NE, 0, 1.f}, 16);
    reduce4<<<dim3((int)(NE / 4 / 256), 1, 4), 256>>>();

    // 6) ms_b = U_b @ wv_b  (NT with B = WvT[b])  [268x1024]
    launch_gemm({U, WvT, MSp, cN, 1024, 1024, 1024, 1024, 1024,
                 0, (long)NE, 0, (long)MM, 0, (long)NE, 0, 1, 1.f}, 4);

    // 7) stage-2 scores: P2[n][tm2] = scale * q~2 @ ms^T (ms as 1072 x 1024)
    launch_gemm({QH + 4 * NE, MSp, P2, cN, 4 * cN, 1024, 1024, 1024, (long)(4 * cN),
                 0, 0, 0, 0, 0, 0, 0, 0, cScale}, 1);
    softmax_kernel<<<(4 * cN + 7) / 8, 256>>>(P2, 4 * cN);

    // 8) U2 = P2 @ ms  (needs ms^T [1024][1072])
    transpose_g<<<dim3(32, (4 * cN + 31) / 32, 1), dim3(32, 8)>>>(MSp, MST, 4 * cN, 1024);
    launch_gemm({P2, MST, U2, cN, 1024, 4 * cN, 4 * cN, 4 * cN, 1024,
                 0, 0, 0, 0, 0, 0, 0, 1, 1.f}, 1);

    // 9) out = U2 @ wv  (NT with B = WvT[4])
    launch_gemm({U2, WvT + 4 * MM, out, cN, 1024, 1024, 1024, 1024, 1024,
                 0, 0, 0, 0, 0, 0, 0, 0, 1.f}, 1);
}